// round 12
// baseline (speedup 1.0000x reference)
#include <cuda_runtime.h>
#include <cuda_fp16.h>

#define TEXN   1024
#define TT     (TEXN * TEXN)
#define CH     16
#define BB     4
#define HH     768
#define WW     768
#define HW     (HH * WW)
#define NPIX   (BB * HW)

#define CLAMP_LO (-123.68f)
#define CLAMP_HI (151.061f)

// Overlapped-block texture layout, fp16:
//   row y = 342 blocks of 128B; block m holds texels 3m..3m+3 (16 ch, 32B
//   per texel). Any bilinear pair (x0,x0+1) sits fully inside block
//   floor(x0/3) -> the 64B gather span NEVER crosses a 128B line.
//   Phantom slots (texel >= 1024) are written as zeros each launch; they are
//   only read with bilinear weight exactly 0.
#define NBLK     342                   // ceil(1024/3)
#define RSTRIDE  (NBLK * 128)          // 43776 bytes per row
__device__ __align__(128) __half g_tex[(size_t)TEXN * NBLK * 64];

// ---------------------------------------------------------------------------
// Pass 1 (v2): clamp + fp16 + repack, smem-staged.
// Block = one y row, 384 threads.
//   Phase A: 4096 coalesced float4 loads (16 ch x 256) -> clamp -> fp16 ->
//            smem [c][x] (stride 1040 halves).
//   Phase B: 342 threads gather 64 halves from smem, emit one 128B block.
// Runs at the 112MB DRAM floor (~14us) instead of scalar-read ~20us.
// ---------------------------------------------------------------------------
#define SROW 1040   // halves per channel row in smem (pad vs 1024)

__global__ __launch_bounds__(384)
void clamp_transpose_kernel(const float* __restrict__ data) {
    __shared__ __align__(8) __half s[CH * SROW];

    int tid = threadIdx.x;
    int y   = blockIdx.x;

    // Phase A: coalesced read + clamp + convert
    const float* row = data + (size_t)y * TEXN;
    for (int i = tid; i < CH * 256; i += 384) {
        int c  = i >> 8;
        int xq = i & 255;
        float4 v = __ldcs(reinterpret_cast<const float4*>(row + (size_t)c * TT + xq * 4));
        v.x = fminf(fmaxf(v.x, CLAMP_LO), CLAMP_HI);
        v.y = fminf(fmaxf(v.y, CLAMP_LO), CLAMP_HI);
        v.z = fminf(fmaxf(v.z, CLAMP_LO), CLAMP_HI);
        v.w = fminf(fmaxf(v.w, CLAMP_LO), CLAMP_HI);
        __half2 h0 = __floats2half2_rn(v.x, v.y);
        __half2 h1 = __floats2half2_rn(v.z, v.w);
        __half2* dst = reinterpret_cast<__half2*>(&s[c * SROW + xq * 4]);
        dst[0] = h0;
        dst[1] = h1;
    }

    __syncthreads();

    // Phase B: gather-transpose into overlapped 128B blocks
    int m = tid;
    if (m >= NBLK) return;
    int xbase = 3 * m;

    __half outh[64];                   // 4 slots x 16 ch
#pragma unroll
    for (int j = 0; j < 4; j++) {
        int x = xbase + j;
        bool valid = (x < TEXN);
#pragma unroll
        for (int c = 0; c < CH; c++)
            outh[j * 16 + c] = valid ? s[c * SROW + x] : __half(0.0f);
    }

    uint4* dst = reinterpret_cast<uint4*>(
        reinterpret_cast<char*>(g_tex) + (size_t)y * RSTRIDE + (size_t)m * 128);
    const uint4* srcw = reinterpret_cast<const uint4*>(outh);
#pragma unroll
    for (int i = 0; i < 8; i++)
        dst[i] = srcw[i];
}

// ---------------------------------------------------------------------------
// Pass 2: bilinear sample (R11 shape, proven best): 4 thr/px, 2 px/thread,
// 128-thr blocks. Texture loads via __ldcg (L2-only: random gathers have
// ~0% L1 hit-rate; skip L1 tag churn).
// ---------------------------------------------------------------------------
#define SOUT_STRIDE 68

struct PixIn {
    uint4 u0, u1;
    float wx, wy;
};

__device__ __forceinline__ void load_pix(float2 g, const char* tbase,
                                         unsigned qoff, PixIn& p) {
    float ix = fminf(fmaxf(fmaf(g.x, 511.5f, 511.5f), 0.0f), 1023.0f);
    float iy = fminf(fmaxf(fmaf(g.y, 511.5f, 511.5f), 0.0f), 1023.0f);
    float x0f = floorf(ix), y0f = floorf(iy);
    p.wx = ix - x0f; p.wy = iy - y0f;
    int x0 = (int)x0f, y0 = (int)y0f;
    unsigned m = ((unsigned)x0 * 43691u) >> 17;     // x0/3 (exact, x0<196K)
    unsigned o = (unsigned)x0 - 3u * m;             // 0..2
    unsigned r0 = (unsigned)y0 * (unsigned)RSTRIDE + (m << 7) + (o << 5) + qoff;
    unsigned r1 = r0 + ((y0 < TEXN - 1) ? (unsigned)RSTRIDE : 0u);
    p.u0 = __ldcg(reinterpret_cast<const uint4*>(tbase + r0));
    p.u1 = __ldcg(reinterpret_cast<const uint4*>(tbase + r1));
}

__device__ __forceinline__ void compute_pix(const PixIn& p, bool hiX, float* res) {
    unsigned recv0a = __shfl_xor_sync(0xffffffffu, hiX ? p.u0.x : p.u0.z, 2);
    unsigned recv0b = __shfl_xor_sync(0xffffffffu, hiX ? p.u0.y : p.u0.w, 2);
    unsigned recv1a = __shfl_xor_sync(0xffffffffu, hiX ? p.u1.x : p.u1.z, 2);
    unsigned recv1b = __shfl_xor_sync(0xffffffffu, hiX ? p.u1.y : p.u1.w, 2);

    unsigned own0a = hiX ? p.u0.z : p.u0.x;
    unsigned own0b = hiX ? p.u0.w : p.u0.y;
    unsigned own1a = hiX ? p.u1.z : p.u1.x;
    unsigned own1b = hiX ? p.u1.w : p.u1.y;

    float w_own = hiX ? p.wx : (1.0f - p.wx);
    __half2 wo2 = __float2half2_rn(w_own);
    __half2 wt2 = __float2half2_rn(1.0f - w_own);

    __half2 r0a = __hfma2(*reinterpret_cast<const __half2*>(&recv0a), wt2,
                  __hmul2(*reinterpret_cast<const __half2*>(&own0a), wo2));
    __half2 r0b = __hfma2(*reinterpret_cast<const __half2*>(&recv0b), wt2,
                  __hmul2(*reinterpret_cast<const __half2*>(&own0b), wo2));
    __half2 r1a = __hfma2(*reinterpret_cast<const __half2*>(&recv1a), wt2,
                  __hmul2(*reinterpret_cast<const __half2*>(&own1a), wo2));
    __half2 r1b = __hfma2(*reinterpret_cast<const __half2*>(&recv1b), wt2,
                  __hmul2(*reinterpret_cast<const __half2*>(&own1b), wo2));

    float2 f0a = __half22float2(r0a);
    float2 f0b = __half22float2(r0b);
    float2 f1a = __half22float2(r1a);
    float2 f1b = __half22float2(r1b);

    res[0] = f0a.x + (f1a.x - f0a.x) * p.wy;
    res[1] = f0a.y + (f1a.y - f0a.y) * p.wy;
    res[2] = f0b.x + (f1b.x - f0b.x) * p.wy;
    res[3] = f0b.y + (f1b.y - f0b.y) * p.wy;
}

__global__ __launch_bounds__(128)
void sample_kernel(const float2* __restrict__ grid, float* __restrict__ out) {
    __shared__ __align__(16) float s_out[CH * SOUT_STRIDE];

    int tid = threadIdx.x;
    int lp  = tid >> 2;                   // 0..31; px lp and lp+32
    int q   = tid & 3;
    int base = blockIdx.x * 64;

    float2 g0 = __ldcs(&grid[base + lp]);
    float2 g1 = __ldcs(&grid[base + lp + 32]);

    const char* tbase = reinterpret_cast<const char*>(g_tex);
    unsigned qoff = (unsigned)q << 4;

    PixIn p0, p1;
    load_pix(g0, tbase, qoff, p0);
    load_pix(g1, tbase, qoff, p1);

    bool hiX = (q & 2) != 0;
    float res0[4], res1[4];
    compute_pix(p0, hiX, res0);
    compute_pix(p1, hiX, res1);

    int ch   = (q & 1) * 8 + (q & 2) * 2;  // 0-3,8-11,4-7,12-15
    int col0 = lp ^ ((q & 1) << 3);
#pragma unroll
    for (int j = 0; j < 4; j++) {
        s_out[(ch + j) * SOUT_STRIDE + col0]      = res0[j];
        s_out[(ch + j) * SOUT_STRIDE + col0 + 32] = res1[j];
    }

    __syncthreads();

    int b  = base / HW;
    int hw = base - b * HW;
#pragma unroll
    for (int r = 0; r < 2; r++) {
        int idx = tid + r * 128;
        int c = idx >> 4;
        int v = idx & 15;
        int vv = v ^ (((c >> 3) & 1) << 1);
        float4 val = *reinterpret_cast<const float4*>(&s_out[c * SOUT_STRIDE + vv * 4]);
        float* o = out + ((size_t)b * CH + c) * HW + hw + v * 4;
        __stcs(reinterpret_cast<float4*>(o), val);
    }
}

extern "C" void kernel_launch(void* const* d_in, const int* in_sizes, int n_in,
                              void* d_out, int out_size) {
    const float* x_grid = (const float*)d_in[0];
    const float* data   = (const float*)d_in[1];
    if (n_in >= 2 && in_sizes[0] == TT * CH) {
        data   = (const float*)d_in[0];
        x_grid = (const float*)d_in[1];
    }

    float* out = (float*)d_out;

    clamp_transpose_kernel<<<TEXN, 384>>>(data);           // 1024 blocks
    sample_kernel<<<NPIX / 64, 128>>>((const float2*)x_grid, out);
}

// round 14
// speedup vs baseline: 1.2096x; 1.2096x over previous
#include <cuda_runtime.h>
#include <cuda_fp16.h>

#define TEXN   1024
#define TT     (TEXN * TEXN)
#define CH     16
#define BB     4
#define HH     768
#define WW     768
#define HW     (HH * WW)
#define NPIX   (BB * HW)

#define CLAMP_LO (-123.68f)
#define CLAMP_HI (151.061f)

// Overlapped-block texture layout, fp16:
//   row y = 342 blocks of 128B; block m holds texels 3m..3m+3 (16 ch, 32B
//   per texel). Any bilinear pair (x0,x0+1) sits fully inside block
//   floor(x0/3) -> the 64B gather span NEVER crosses a 128B line.
//   Phantom slots (texel >= 1024) are NEVER written: static zero-init gives
//   them 0 forever; they are only read with bilinear weight exactly 0.
#define NBLK     342                   // ceil(1024/3)
#define RSTRIDE  (NBLK * 128)          // 43776 bytes per row
__device__ __align__(128) __half g_tex[(size_t)TEXN * NBLK * 64];

// ---------------------------------------------------------------------------
// Pass 1 (v3): source-driven clamp + fp16 + repack. One thread per texel.
//   Reads:  16 fully-coalesced LDG.32 (1 line/instr) + clamp + cvt.
//   Writes: texel's 32B to its primary slot (block x/3, off (x%3)*32);
//           x % 3 == 0 additionally duplicates into block x/3-1 slot 3.
//   Near-coalesced writes; pass runs at the 112MB DRAM floor.
// ---------------------------------------------------------------------------
__global__ __launch_bounds__(256)
void clamp_repack_kernel(const float* __restrict__ data) {
    int x = blockIdx.x * 256 + threadIdx.x;   // 0..1023
    int y = blockIdx.y;                       // 0..1023

    const float* src = data + (size_t)y * TEXN + x;
    __align__(16) __half h[CH];
#pragma unroll
    for (int c = 0; c < CH; c++) {
        float v = __ldcs(src + (size_t)c * TT);
        h[c] = __float2half_rn(fminf(fmaxf(v, CLAMP_LO), CLAMP_HI));
    }
    const uint4* w = reinterpret_cast<const uint4*>(h);

    unsigned m1 = ((unsigned)x * 43691u) >> 17;   // x/3 exact for x < 196K
    unsigned o1 = (unsigned)x - 3u * m1;          // 0..2
    char* rowbase = reinterpret_cast<char*>(g_tex) + (size_t)y * RSTRIDE;

    uint4* d1 = reinterpret_cast<uint4*>(rowbase + (m1 << 7) + (o1 << 5));
    d1[0] = w[0];
    d1[1] = w[1];

    if (o1 == 0u && m1 > 0u) {                    // texel 3m also = slot 3 of block m-1
        uint4* d2 = reinterpret_cast<uint4*>(rowbase + ((m1 - 1u) << 7) + 96u);
        d2[0] = w[0];
        d2[1] = w[1];
    }
}

// ---------------------------------------------------------------------------
// Pass 2: bilinear sample (proven best shape): 4 thr/px, 2 px/thread,
// 128-thr blocks, __ldcg texture gathers (L2-only), smem-staged writeback.
// ---------------------------------------------------------------------------
#define SOUT_STRIDE 68

struct PixIn {
    uint4 u0, u1;
    float wx, wy;
};

__device__ __forceinline__ void load_pix(float2 g, const char* tbase,
                                         unsigned qoff, PixIn& p) {
    float ix = fminf(fmaxf(fmaf(g.x, 511.5f, 511.5f), 0.0f), 1023.0f);
    float iy = fminf(fmaxf(fmaf(g.y, 511.5f, 511.5f), 0.0f), 1023.0f);
    float x0f = floorf(ix), y0f = floorf(iy);
    p.wx = ix - x0f; p.wy = iy - y0f;
    int x0 = (int)x0f, y0 = (int)y0f;
    unsigned m = ((unsigned)x0 * 43691u) >> 17;
    unsigned o = (unsigned)x0 - 3u * m;
    unsigned r0 = (unsigned)y0 * (unsigned)RSTRIDE + (m << 7) + (o << 5) + qoff;
    unsigned r1 = r0 + ((y0 < TEXN - 1) ? (unsigned)RSTRIDE : 0u);
    p.u0 = __ldcg(reinterpret_cast<const uint4*>(tbase + r0));
    p.u1 = __ldcg(reinterpret_cast<const uint4*>(tbase + r1));
}

__device__ __forceinline__ void compute_pix(const PixIn& p, bool hiX, float* res) {
    unsigned recv0a = __shfl_xor_sync(0xffffffffu, hiX ? p.u0.x : p.u0.z, 2);
    unsigned recv0b = __shfl_xor_sync(0xffffffffu, hiX ? p.u0.y : p.u0.w, 2);
    unsigned recv1a = __shfl_xor_sync(0xffffffffu, hiX ? p.u1.x : p.u1.z, 2);
    unsigned recv1b = __shfl_xor_sync(0xffffffffu, hiX ? p.u1.y : p.u1.w, 2);

    unsigned own0a = hiX ? p.u0.z : p.u0.x;
    unsigned own0b = hiX ? p.u0.w : p.u0.y;
    unsigned own1a = hiX ? p.u1.z : p.u1.x;
    unsigned own1b = hiX ? p.u1.w : p.u1.y;

    float w_own = hiX ? p.wx : (1.0f - p.wx);
    __half2 wo2 = __float2half2_rn(w_own);
    __half2 wt2 = __float2half2_rn(1.0f - w_own);

    __half2 r0a = __hfma2(*reinterpret_cast<const __half2*>(&recv0a), wt2,
                  __hmul2(*reinterpret_cast<const __half2*>(&own0a), wo2));
    __half2 r0b = __hfma2(*reinterpret_cast<const __half2*>(&recv0b), wt2,
                  __hmul2(*reinterpret_cast<const __half2*>(&own0b), wo2));
    __half2 r1a = __hfma2(*reinterpret_cast<const __half2*>(&recv1a), wt2,
                  __hmul2(*reinterpret_cast<const __half2*>(&own1a), wo2));
    __half2 r1b = __hfma2(*reinterpret_cast<const __half2*>(&recv1b), wt2,
                  __hmul2(*reinterpret_cast<const __half2*>(&own1b), wo2));

    float2 f0a = __half22float2(r0a);
    float2 f0b = __half22float2(r0b);
    float2 f1a = __half22float2(r1a);
    float2 f1b = __half22float2(r1b);

    res[0] = f0a.x + (f1a.x - f0a.x) * p.wy;
    res[1] = f0a.y + (f1a.y - f0a.y) * p.wy;
    res[2] = f0b.x + (f1b.x - f0b.x) * p.wy;
    res[3] = f0b.y + (f1b.y - f0b.y) * p.wy;
}

__global__ __launch_bounds__(128)
void sample_kernel(const float2* __restrict__ grid, float* __restrict__ out) {
    __shared__ __align__(16) float s_out[CH * SOUT_STRIDE];

    int tid = threadIdx.x;
    int lp  = tid >> 2;                   // 0..31; px lp and lp+32
    int q   = tid & 3;
    int base = blockIdx.x * 64;

    float2 g0 = __ldcs(&grid[base + lp]);
    float2 g1 = __ldcs(&grid[base + lp + 32]);

    const char* tbase = reinterpret_cast<const char*>(g_tex);
    unsigned qoff = (unsigned)q << 4;

    PixIn p0, p1;
    load_pix(g0, tbase, qoff, p0);
    load_pix(g1, tbase, qoff, p1);

    bool hiX = (q & 2) != 0;
    float res0[4], res1[4];
    compute_pix(p0, hiX, res0);
    compute_pix(p1, hiX, res1);

    int ch   = (q & 1) * 8 + (q & 2) * 2;  // 0-3,8-11,4-7,12-15
    int col0 = lp ^ ((q & 1) << 3);
#pragma unroll
    for (int j = 0; j < 4; j++) {
        s_out[(ch + j) * SOUT_STRIDE + col0]      = res0[j];
        s_out[(ch + j) * SOUT_STRIDE + col0 + 32] = res1[j];
    }

    __syncthreads();

    int b  = base / HW;
    int hw = base - b * HW;
#pragma unroll
    for (int r = 0; r < 2; r++) {
        int idx = tid + r * 128;
        int c = idx >> 4;
        int v = idx & 15;
        int vv = v ^ (((c >> 3) & 1) << 1);
        float4 val = *reinterpret_cast<const float4*>(&s_out[c * SOUT_STRIDE + vv * 4]);
        float* o = out + ((size_t)b * CH + c) * HW + hw + v * 4;
        __stcs(reinterpret_cast<float4*>(o), val);
    }
}

extern "C" void kernel_launch(void* const* d_in, const int* in_sizes, int n_in,
                              void* d_out, int out_size) {
    const float* x_grid = (const float*)d_in[0];
    const float* data   = (const float*)d_in[1];
    if (n_in >= 2 && in_sizes[0] == TT * CH) {
        data   = (const float*)d_in[0];
        x_grid = (const float*)d_in[1];
    }

    float* out = (float*)d_out;

    clamp_repack_kernel<<<dim3(4, 1024), 256>>>(data);     // 1 thread/texel
    sample_kernel<<<NPIX / 64, 128>>>((const float2*)x_grid, out);
}